// round 8
// baseline (speedup 1.0000x reference)
#include <cuda_runtime.h>
#include <cstdint>

#define N 8400
#define WORDS 132          // ceil(8400/64)
#define SCORE_THR 0.5f
#define IOU_THR 0.5f
#define GRID 136           // <= 148 SMs: all blocks co-resident (wave 1)
#define NT 256

typedef unsigned long long u64;

// ---- persistent device state (allocation-free rule) ----
__device__ int g_vcount = 0;
__device__ int g_bar_arrive = 0;
__device__ volatile int g_bar_release = 0;
__device__ int g_bar_exit = 0;
__device__ u64 g_vkey[N];
__device__ float4 g_vbox[N];
__device__ float g_vscore[N];
__device__ int g_rankp[8][N];
__device__ float4 g_sbox[N];
__device__ float g_sscore[N];
__device__ u64 g_mask[N][WORDS];

// Software grid barrier (all CTAs co-resident since GRID < #SMs).
__device__ __forceinline__ void gbar(int gen) {
    __syncthreads();
    if (threadIdx.x == 0) {
        __threadfence();
        int prev = atomicAdd(&g_bar_arrive, 1);
        if (prev == gen * GRID - 1) {
            g_bar_release = gen;
        } else {
            while (g_bar_release < gen) { }
        }
        __threadfence();
    }
    __syncthreads();
}

__device__ __forceinline__ void cpa16(uint32_t saddr, const void* gptr) {
    asm volatile("cp.async.cg.shared.global [%0], [%1], 16;"
                 :: "r"(saddr), "l"(gptr));
}

__global__ __launch_bounds__(NT) void k_all(const float* __restrict__ in,
                                            float* __restrict__ out) {
    extern __shared__ __align__(16) char dyn[];   // 17,408B scratch
    __shared__ u64 remv[WORDS];
    __shared__ unsigned s_nzw[8];
    int tid = threadIdx.x;
    int bid = blockIdx.x;
    int gtid = bid * NT + tid;

    // ---------------- Phase 1: decode + compact valid ----------------------
    {
        int a = gtid;
        int lane = tid & 31;
        bool valid = false;
        float4 b = make_float4(0.f, 0.f, 0.f, 0.f);
        float s = 0.f;
        u64 key = 0ull;
        if (a < N) {
            float cx = in[a];
            float cy = in[N + a];
            float w  = in[2 * N + a];
            float h  = in[3 * N + a];
            s = in[4 * N + a];
            float hw = __fmul_rn(w, 0.5f);
            float hh = __fmul_rn(h, 0.5f);
            b.x = __fsub_rn(cx, hw);
            b.y = __fsub_rn(cy, hh);
            b.z = __fadd_rn(cx, hw);
            b.w = __fadd_rn(cy, hh);
            valid = (s >= SCORE_THR);
            key = (((u64)__float_as_uint(s)) << 14) | (u64)(16383 - a);
        }
        unsigned m = __ballot_sync(0xffffffffu, valid);
        if (m != 0u) {
            int leader = __ffs(m) - 1;
            int base = 0;
            if (lane == leader) base = atomicAdd(&g_vcount, __popc(m));
            base = __shfl_sync(0xffffffffu, base, leader);
            if (valid) {
                int pos = base + __popc(m & ((1u << lane) - 1u));
                g_vkey[pos]   = key;
                g_vbox[pos]   = b;
                g_vscore[pos] = s;
            }
        }
    }
    gbar(1);
    int V = *(volatile int*)&g_vcount;

    // ---------------- Phase 2: rank partials (i-blocks x 8 j-chunks) -------
    {
        u64* sk = (u64*)dyn;
        int IB = (V + NT - 1) / NT;
        int CH = (V + 7) / 8;
        int ntasks = IB * 8;
        for (int task = bid; task < ntasks; task += GRID) {
            int ib = task % IB;
            int jb = task / IB;
            int jlo = jb * CH;
            int mlen = min(jlo + CH, V) - jlo;
            __syncthreads();
            for (int d = tid; d < mlen; d += NT)
                sk[d] = g_vkey[jlo + d];
            __syncthreads();
            int p = ib * NT + tid;
            u64 kp = (p < V) ? g_vkey[p] : 0ull;
            int cnt = 0;
#pragma unroll 8
            for (int d = 0; d < mlen; ++d)
                cnt += (sk[d] > kp) ? 1 : 0;
            if (p < V) g_rankp[jb][p] = cnt;
        }
    }
    gbar(2);

    // ---------------- Phase 3: sum partials + scatter -----------------------
    for (int p = gtid; p < V; p += GRID * NT) {
        int r = 0;
#pragma unroll
        for (int y = 0; y < 8; ++y) r += g_rankp[y][p];
        g_sbox[r]   = g_vbox[p];
        g_sscore[r] = g_vscore[p];
    }
    gbar(3);

    // ---------------- Phase 4: IoU bitmask (128x128 triangle tiles) --------
    {
        float4* cbox  = (float4*)dyn;
        float*  carea = (float*)(dyn + 128 * 16);
        int Tv = (V + 127) >> 7;
        int ntasks = Tv * (Tv + 1) / 2;
        for (int task = bid; task < ntasks; task += GRID) {
            int t2 = task, rb = 0;
            while (t2 >= Tv - rb) { t2 -= Tv - rb; rb++; }
            int cb = rb + t2;
            __syncthreads();
            if (tid < 128) {
                int j = cb * 128 + tid;
                if (j < V) {
                    float4 b = g_sbox[j];
                    cbox[tid] = b;
                    carea[tid] = __fmul_rn(__fsub_rn(b.z, b.x),
                                           __fsub_rn(b.w, b.y));
                } else {
                    cbox[tid] = make_float4(0.f, 0.f, 0.f, 0.f);
                    carea[tid] = 0.f;
                }
            }
            __syncthreads();
            int row = tid & 127;
            int half = tid >> 7;
            int i = rb * 128 + row;
            if (i < V) {
                float4 bi = g_sbox[i];
                float ai = __fmul_rn(__fsub_rn(bi.z, bi.x),
                                     __fsub_rn(bi.w, bi.y));
                int cbase = half * 64;
                int wordbase = cb * 128 + cbase;
                int dstart = max(0, i + 1 - wordbase);
                u64 bits = 0ull;
                for (int d = dstart; d < 64; ++d) {
                    float4 bj = cbox[cbase + d];
                    float ltx = fmaxf(bi.x, bj.x);
                    float lty = fmaxf(bi.y, bj.y);
                    float rbx = fminf(bi.z, bj.z);
                    float rby = fminf(bi.w, bj.w);
                    float wx = fmaxf(__fsub_rn(rbx, ltx), 0.0f);
                    float wy = fmaxf(__fsub_rn(rby, lty), 0.0f);
                    float inter = __fmul_rn(wx, wy);
                    float uni = __fsub_rn(__fadd_rn(ai, carea[cbase + d]), inter);
                    float den = fmaxf(uni, 1e-9f);
                    bool hit;
                    if (inter > __fmul_rn(0.5005f, den))      hit = true;
                    else if (inter < __fmul_rn(0.4995f, den)) hit = false;
                    else hit = (__fdiv_rn(inter, den) > IOU_THR);
                    if (hit) bits |= (1ull << d);
                }
                g_mask[i][cb * 2 + half] = bits;
            }
        }
    }
    gbar(4);

    // ---------------- Phase 5: block 0 — 256-row-tile reduce + output ------
    if (bid != 0) {
        __syncthreads();
        if (tid == 0) atomicAdd(&g_bar_exit, 1);
        return;
    }

    int Tc = (V + 63) >> 6;             // valid mask words
    int TT = (V + 255) >> 8;            // 256-row tiles (<= 33)
    __syncthreads();
    // init remv: bit p set iff p >= V
    for (int w = tid; w < WORDS; w += NT) {
        int base = w * 64;
        u64 m;
        if (base + 64 <= V)      m = 0ull;
        else if (base >= V)      m = ~0ull;
        else                     m = (~0ull) << (V - base);
        remv[w] = m;
    }
    __syncthreads();

    if (TT > 0) {
        u64 (*diag)[256][4] = (u64 (*)[256][4])dyn;   // 2 x 256 x 4 x 8B = 16KB
        // stage tile 0 diagonal block (words 0..3 of rows 0..255)
        for (int u = tid; u < 512; u += NT) {
            int r = u >> 1, pr = u & 1;
            int i = min(r, N - 1);
            cpa16((uint32_t)__cvta_generic_to_shared(&diag[0][r][pr * 2]),
                  &g_mask[i][pr * 2]);
        }
        asm volatile("cp.async.commit_group;");

        for (int tt = 0; tt < TT; ++tt) {
            int cur = tt & 1;
            asm volatile("cp.async.wait_group 0;" ::: "memory");
            __syncthreads();
            if (tt + 1 < TT) {          // prefetch next diagonal block
                int ibase = (tt + 1) * 256;
                int wb = (tt + 1) * 4;
                for (int u = tid; u < 512; u += NT) {
                    int r = u >> 1, pr = u & 1;
                    int i = min(ibase + r, N - 1);
                    cpa16((uint32_t)__cvta_generic_to_shared(&diag[cur ^ 1][r][pr * 2]),
                          &g_mask[i][wb + pr * 2]);
                }
                asm volatile("cp.async.commit_group;");
            }
            // nz: does row tid have any (valid-triangle) nonzero diag word?
            {
                int k0 = tid >> 6;
                u64 rowor = 0ull;
                for (int m = k0; m < 4; ++m) rowor |= diag[cur][tid][m];
                unsigned bal = __ballot_sync(0xffffffffu, rowor != 0ull);
                if ((tid & 31) == 0) s_nzw[tid >> 5] = bal;
            }
            __syncthreads();
            if (tid == 0) {             // serial greedy scan over 256 rows
                u64 cw[4], nz[4];
#pragma unroll
                for (int k = 0; k < 4; ++k) {
                    cw[k] = remv[tt * 4 + k];
                    nz[k] = (u64)s_nzw[2 * k] | ((u64)s_nzw[2 * k + 1] << 32);
                }
#pragma unroll
                for (int k = 0; k < 4; ++k) {
                    u64 cand = nz[k] & ~cw[k];
                    while (cand) {
                        int b = __ffsll(cand) - 1;
                        int r = (k << 6) | b;
                        for (int m = k; m < 4; ++m) cw[m] |= diag[cur][r][m];
                        u64 below = (b == 63) ? ~0ull : ((2ull << b) - 1ull);
                        cand = nz[k] & ~cw[k] & ~below;
                    }
                }
#pragma unroll
                for (int k = 0; k < 4; ++k) remv[tt * 4 + k] = cw[k];
            }
            __syncthreads();
            // OR phase: word w > this tile; kept rows' masks from L2 (MLP)
            int wbase = (tt + 1) * 4;
            for (int w = wbase + tid; w < Tc; w += NT) {
                u64 acc = remv[w];
                const u64* mbase = &g_mask[tt * 256][0];
#pragma unroll
                for (int k = 0; k < 4; ++k) {
                    u64 kk = ~remv[tt * 4 + k];     // kept rows (< V only)
                    while (kk) {
                        int b = __ffsll(kk) - 1;
                        kk &= kk - 1;
                        acc |= mbase[(size_t)((k << 6) | b) * WORDS + w];
                    }
                }
                remv[w] = acc;
            }
            __syncthreads();
        }
    }

    // output: kept -> [x1,y1,x2,y2,score], else zeros
    for (int p = tid; p < N; p += NT) {
        bool kept = (p < V) && !((remv[p >> 6] >> (p & 63)) & 1ull);
        float4 b = kept ? g_sbox[p] : make_float4(0.f, 0.f, 0.f, 0.f);
        float s = kept ? g_sscore[p] : 0.f;
        out[p * 5 + 0] = b.x;
        out[p * 5 + 1] = b.y;
        out[p * 5 + 2] = b.z;
        out[p * 5 + 3] = b.w;
        out[p * 5 + 4] = s;
    }

    // reset persistent state for the next graph replay
    __syncthreads();
    if (tid == 0) {
        while (*(volatile int*)&g_bar_exit < GRID - 1) { }
        g_bar_exit = 0;
        g_bar_arrive = 0;
        g_bar_release = 0;
        g_vcount = 0;
        __threadfence();
    }
}

extern "C" void kernel_launch(void* const* d_in, const int* in_sizes, int n_in,
                              void* d_out, int out_size) {
    const float* in = (const float*)d_in[0];
    float* out = (float*)d_out;
    k_all<<<GRID, NT, 17408>>>(in, out);
}

// round 9
// speedup vs baseline: 1.8590x; 1.8590x over previous
#include <cuda_runtime.h>
#include <cstdint>

#define N 8400
#define WORDS 132          // ceil(8400/64)
#define SCORE_THR 0.5f
#define IOU_THR 0.5f
#define GRID 136           // <= 148 SMs: all blocks co-resident (wave 1)
#define NT 256
#define NPAD 8448          // N rounded up (16B staging granularity)

typedef unsigned long long u64;

struct __align__(16) SpEnt { u64 bits; u64 idx; };

// ---- persistent device state (allocation-free rule) ----
__device__ int g_vcount = 0;
__device__ int g_bar_arrive = 0;
__device__ volatile int g_bar_release = 0;
__device__ int g_bar_exit = 0;
__device__ u64 g_vkey[N];
__device__ float4 g_vbox[N];
__device__ float g_vscore[N];
__device__ int g_rankp[8][N];
__device__ float4 g_sbox[N];
__device__ float g_sscore[N];
__device__ u64 g_diag[NPAD];               // row's own diagonal mask word
__device__ unsigned g_scount[NPAD];        // row's # of sparse off-diag entries
__device__ SpEnt g_slist[N][WORDS];        // sparse nonzero off-diag words

// Software grid barrier (all CTAs co-resident since GRID < #SMs).
__device__ __forceinline__ void gbar(int gen) {
    __syncthreads();
    if (threadIdx.x == 0) {
        __threadfence();
        int prev = atomicAdd(&g_bar_arrive, 1);
        if (prev == gen * GRID - 1) {
            g_bar_release = gen;
        } else {
            while (g_bar_release < gen) { }
        }
        __threadfence();
    }
    __syncthreads();
}

__device__ __forceinline__ void cpa16(uint32_t saddr, const void* gptr) {
    asm volatile("cp.async.cg.shared.global [%0], [%1], 16;"
                 :: "r"(saddr), "l"(gptr));
}

__global__ __launch_bounds__(NT) void k_all(const float* __restrict__ in,
                                            float* __restrict__ out) {
    extern __shared__ __align__(16) char dyn[];   // 101,376B
    u64*      sdiag = (u64*)dyn;                  // [NPAD] 67,584B
    unsigned* sscnt = (unsigned*)(dyn + NPAD * 8);// [NPAD] 33,792B
    __shared__ u64 remv[WORDS];
    __shared__ unsigned s_nz32[2 * WORDS];
    int tid = threadIdx.x;
    int bid = blockIdx.x;
    int gtid = bid * NT + tid;

    // ---------------- Phase 1: decode + compact valid ----------------------
    {
        int a = gtid;
        int lane = tid & 31;
        bool valid = false;
        float4 b = make_float4(0.f, 0.f, 0.f, 0.f);
        float s = 0.f;
        u64 key = 0ull;
        if (a < N) {
            float cx = in[a];
            float cy = in[N + a];
            float w  = in[2 * N + a];
            float h  = in[3 * N + a];
            s = in[4 * N + a];
            float hw = __fmul_rn(w, 0.5f);
            float hh = __fmul_rn(h, 0.5f);
            b.x = __fsub_rn(cx, hw);
            b.y = __fsub_rn(cy, hh);
            b.z = __fadd_rn(cx, hw);
            b.w = __fadd_rn(cy, hh);
            valid = (s >= SCORE_THR);
            key = (((u64)__float_as_uint(s)) << 14) | (u64)(16383 - a);
            g_scount[a] = 0u;                      // reset sparse counts
        }
        unsigned m = __ballot_sync(0xffffffffu, valid);
        if (m != 0u) {
            int leader = __ffs(m) - 1;
            int base = 0;
            if (lane == leader) base = atomicAdd(&g_vcount, __popc(m));
            base = __shfl_sync(0xffffffffu, base, leader);
            if (valid) {
                int pos = base + __popc(m & ((1u << lane) - 1u));
                g_vkey[pos]   = key;
                g_vbox[pos]   = b;
                g_vscore[pos] = s;
            }
        }
    }
    gbar(1);
    int V = *(volatile int*)&g_vcount;

    // ---------------- Phase 2: rank partials (i-blocks x 8 j-chunks) -------
    {
        u64* sk = (u64*)dyn;
        int IB = (V + NT - 1) / NT;
        int CH = (V + 7) / 8;
        int ntasks = IB * 8;
        for (int task = bid; task < ntasks; task += GRID) {
            int ib = task % IB;
            int jb = task / IB;
            int jlo = jb * CH;
            int mlen = min(jlo + CH, V) - jlo;
            __syncthreads();
            for (int d = tid; d < mlen; d += NT)
                sk[d] = g_vkey[jlo + d];
            __syncthreads();
            int p = ib * NT + tid;
            u64 kp = (p < V) ? g_vkey[p] : 0ull;
            int cnt = 0;
#pragma unroll 8
            for (int d = 0; d < mlen; ++d)
                cnt += (sk[d] > kp) ? 1 : 0;
            if (p < V) g_rankp[jb][p] = cnt;
        }
    }
    gbar(2);

    // ---------------- Phase 3: sum partials + scatter -----------------------
    for (int p = gtid; p < V; p += GRID * NT) {
        int r = 0;
#pragma unroll
        for (int y = 0; y < 8; ++y) r += g_rankp[y][p];
        g_sbox[r]   = g_vbox[p];
        g_sscore[r] = g_vscore[p];
    }
    gbar(3);

    // ---------------- Phase 4: IoU -> diag word + sparse off-diag entries --
    {
        float4* cbox  = (float4*)dyn;
        float*  carea = (float*)(dyn + 128 * 16);
        int Tv = (V + 127) >> 7;
        int ntasks = Tv * (Tv + 1) / 2;
        for (int task = bid; task < ntasks; task += GRID) {
            int t2 = task, rb = 0;
            while (t2 >= Tv - rb) { t2 -= Tv - rb; rb++; }
            int cb = rb + t2;
            __syncthreads();
            if (tid < 128) {
                int j = cb * 128 + tid;
                if (j < V) {
                    float4 b = g_sbox[j];
                    cbox[tid] = b;
                    carea[tid] = __fmul_rn(__fsub_rn(b.z, b.x),
                                           __fsub_rn(b.w, b.y));
                } else {
                    cbox[tid] = make_float4(0.f, 0.f, 0.f, 0.f);
                    carea[tid] = 0.f;
                }
            }
            __syncthreads();
            int row = tid & 127;
            int half = tid >> 7;
            int i = rb * 128 + row;
            if (i < V) {
                float4 bi = g_sbox[i];
                float ai = __fmul_rn(__fsub_rn(bi.z, bi.x),
                                     __fsub_rn(bi.w, bi.y));
                int cbase = half * 64;
                int wordbase = cb * 128 + cbase;
                int dstart = max(0, i + 1 - wordbase);
                u64 bits = 0ull;
                for (int d = dstart; d < 64; ++d) {
                    float4 bj = cbox[cbase + d];
                    float ltx = fmaxf(bi.x, bj.x);
                    float lty = fmaxf(bi.y, bj.y);
                    float rbx = fminf(bi.z, bj.z);
                    float rby = fminf(bi.w, bj.w);
                    float wx = fmaxf(__fsub_rn(rbx, ltx), 0.0f);
                    float wy = fmaxf(__fsub_rn(rby, lty), 0.0f);
                    float inter = __fmul_rn(wx, wy);
                    float uni = __fsub_rn(__fadd_rn(ai, carea[cbase + d]), inter);
                    float den = fmaxf(uni, 1e-9f);
                    bool hit;
                    if (inter > __fmul_rn(0.5005f, den))      hit = true;
                    else if (inter < __fmul_rn(0.4995f, den)) hit = false;
                    else hit = (__fdiv_rn(inter, den) > IOU_THR);
                    if (hit) bits |= (1ull << d);
                }
                int w = cb * 2 + half;
                if (w == (i >> 6)) {
                    g_diag[i] = bits;                 // always write diag word
                } else if (bits) {
                    unsigned pos = atomicAdd(&g_scount[i], 1u);
                    SpEnt e; e.bits = bits; e.idx = (u64)w;
                    g_slist[i][pos] = e;
                }
            }
        }
    }
    gbar(4);

    // ---------------- Phase 5: block 0 — sparse greedy reduce + output -----
    if (bid != 0) {
        __syncthreads();
        if (tid == 0) atomicAdd(&g_bar_exit, 1);
        return;
    }

    int T = (V + 63) >> 6;
    __syncthreads();
    // init remv: bit p set iff p >= V
    for (int w = tid; w < WORDS; w += NT) {
        int base = w * 64;
        u64 m;
        if (base + 64 <= V)      m = 0ull;
        else if (base >= V)      m = ~0ull;
        else                     m = (~0ull) << (V - base);
        remv[w] = m;
    }

    // stage g_diag[0..V) and g_scount[0..V) into SMEM (one shot)
    {
        int nd = (V + 1) >> 1;                      // 16B chunks of diag
        for (int u = tid; u < nd; u += NT)
            cpa16((uint32_t)__cvta_generic_to_shared(&sdiag[u * 2]),
                  &g_diag[u * 2]);
        int ns = (V + 3) >> 2;                      // 16B chunks of scount
        for (int u = tid; u < ns; u += NT)
            cpa16((uint32_t)__cvta_generic_to_shared(&sscnt[u * 4]),
                  &g_scount[u * 4]);
        asm volatile("cp.async.commit_group;");
        asm volatile("cp.async.wait_group 0;" ::: "memory");
    }
    __syncthreads();

    // nz bitmap over diag words (once, ballots; 32-row groups)
    for (int c = 0; c < NPAD; c += NT) {
        int r = c + tid;
        bool nzb = (r < V) && (sdiag[r] != 0ull);
        unsigned bal = __ballot_sync(0xffffffffu, nzb);
        if ((tid & 31) == 0) s_nz32[r >> 5] = bal;
    }
    __syncthreads();

    for (int t = 0; t < T; ++t) {
        if (tid == 0) {                             // serial greedy scan (SMEM)
            u64 c = remv[t];
            u64 nz = (u64)s_nz32[2 * t] | ((u64)s_nz32[2 * t + 1] << 32);
            u64 cand = nz & ~c;
            while (cand) {
                int b = __ffsll(cand) - 1;
                c |= sdiag[t * 64 + b];
                u64 below = (b == 63) ? ~0ull : ((2ull << b) - 1ull);
                cand = nz & ~c & ~below;
            }
            remv[t] = c;
        }
        __syncthreads();
        // sparse OR: lanes 0..63 each own one row of this tile
        if (tid < 64) {
            u64 curw = remv[t];
            int r = t * 64 + tid;
            if (r < V && !((curw >> tid) & 1ull)) {     // row kept
                int cnt = (int)sscnt[r];
                const SpEnt* lp = &g_slist[r][0];
                for (int e = 0; e < cnt; ++e) {
                    ulonglong2 ent = *(const ulonglong2*)&lp[e];  // LDG.128
                    int w = (int)ent.y;
                    if (w > t) atomicOr(&remv[w], ent.x);
                }
            }
        }
        __syncthreads();
    }

    // output: kept -> [x1,y1,x2,y2,score], else zeros
    for (int p = tid; p < N; p += NT) {
        bool kept = (p < V) && !((remv[p >> 6] >> (p & 63)) & 1ull);
        float4 b = kept ? g_sbox[p] : make_float4(0.f, 0.f, 0.f, 0.f);
        float s = kept ? g_sscore[p] : 0.f;
        out[p * 5 + 0] = b.x;
        out[p * 5 + 1] = b.y;
        out[p * 5 + 2] = b.z;
        out[p * 5 + 3] = b.w;
        out[p * 5 + 4] = s;
    }

    // reset persistent state for the next graph replay
    __syncthreads();
    if (tid == 0) {
        while (*(volatile int*)&g_bar_exit < GRID - 1) { }
        g_bar_exit = 0;
        g_bar_arrive = 0;
        g_bar_release = 0;
        g_vcount = 0;
        __threadfence();
    }
}

extern "C" void kernel_launch(void* const* d_in, const int* in_sizes, int n_in,
                              void* d_out, int out_size) {
    const float* in = (const float*)d_in[0];
    float* out = (float*)d_out;
    cudaFuncSetAttribute(k_all, cudaFuncAttributeMaxDynamicSharedMemorySize,
                         NPAD * 12);   // 101,376B
    k_all<<<GRID, NT, NPAD * 12>>>(in, out);
}

// round 12
// speedup vs baseline: 2.7695x; 1.4898x over previous
#include <cuda_runtime.h>
#include <cstdint>

#define N 8400
#define WORDS 132          // ceil(8400/64)
#define SCORE_THR 0.5f
#define IOU_THR 0.5f
#define GRID 136           // <= 148 SMs: all blocks co-resident (wave 1)
#define NT 1024
#define JS 32              // rank j-split
#define NPAD 8448          // = 264*32: nz bitmap bound

typedef unsigned long long u64;

struct __align__(16) SpEnt { u64 bits; u64 idx; };

// ---- persistent device state (allocation-free rule) ----
__device__ int g_vcount = 0;
__device__ int g_bar_arrive = 0;
__device__ volatile int g_bar_release = 0;
__device__ int g_bar_exit = 0;
__device__ u64 g_vkey[N];
__device__ float4 g_vbox[N];
__device__ float g_vscore[N];
__device__ int g_rankp[JS][N];
__device__ float4 g_sbox[N];
__device__ float g_sscore[N];
__device__ u64 g_diag[NPAD];               // row's own diagonal mask word
__device__ unsigned g_scount[NPAD];        // row's # of sparse off-diag entries
__device__ SpEnt g_slist[N][WORDS];        // sparse nonzero off-diag words

// Software grid barrier (all CTAs co-resident since GRID < #SMs).
__device__ __forceinline__ void gbar(int gen) {
    __syncthreads();
    if (threadIdx.x == 0) {
        __threadfence();
        int prev = atomicAdd(&g_bar_arrive, 1);
        if (prev == gen * GRID - 1) {
            g_bar_release = gen;
        } else {
            while (g_bar_release < gen) { }
        }
        __threadfence();
    }
    __syncthreads();
}

__device__ __forceinline__ void cpa16(uint32_t saddr, const void* gptr) {
    asm volatile("cp.async.cg.shared.global [%0], [%1], 16;"
                 :: "r"(saddr), "l"(gptr));
}

__global__ __launch_bounds__(NT) void k_all(const float* __restrict__ in,
                                            float* __restrict__ out) {
    extern __shared__ __align__(16) char dyn[];   // 67,584B union scratch
    __shared__ u64 remv[WORDS];
    __shared__ unsigned s_nz32[2 * WORDS];
    int tid = threadIdx.x;
    int bid = blockIdx.x;
    int gtid = bid * NT + tid;

    // ---------------- Phase 1: decode + compact valid ----------------------
    {
        int a = gtid;
        int lane = tid & 31;
        bool valid = false;
        float4 b = make_float4(0.f, 0.f, 0.f, 0.f);
        float s = 0.f;
        u64 key = 0ull;
        if (a < N) {
            float cx = in[a];
            float cy = in[N + a];
            float w  = in[2 * N + a];
            float h  = in[3 * N + a];
            s = in[4 * N + a];
            float hw = __fmul_rn(w, 0.5f);
            float hh = __fmul_rn(h, 0.5f);
            b.x = __fsub_rn(cx, hw);
            b.y = __fsub_rn(cy, hh);
            b.z = __fadd_rn(cx, hw);
            b.w = __fadd_rn(cy, hh);
            valid = (s >= SCORE_THR);
            key = (((u64)__float_as_uint(s)) << 14) | (u64)(16383 - a);
            g_scount[a] = 0u;                      // reset sparse counts
            g_diag[a] = 0ull;                      // reset diag words
        }
        unsigned m = __ballot_sync(0xffffffffu, valid);
        if (m != 0u) {
            int leader = __ffs(m) - 1;
            int base = 0;
            if (lane == leader) base = atomicAdd(&g_vcount, __popc(m));
            base = __shfl_sync(0xffffffffu, base, leader);
            if (valid) {
                int pos = base + __popc(m & ((1u << lane) - 1u));
                g_vkey[pos]   = key;
                g_vbox[pos]   = b;
                g_vscore[pos] = s;
            }
        }
    }
    gbar(1);
    int V = *(volatile int*)&g_vcount;

    // ---------------- Phase 2: rank partials (i-blocks x 32 j-chunks) ------
    {
        u64* sk = (u64*)dyn;                       // up to ~264 keys
        int IB = (V + NT - 1) / NT;
        int CH = (V + JS - 1) / JS;
        int ntasks = IB * JS;
        for (int task = bid; task < ntasks; task += GRID) {
            int ib = task % IB;
            int jb = task / IB;
            int jlo = jb * CH;
            int mlen = min(jlo + CH, V) - jlo;
            __syncthreads();
            for (int d = tid; d < mlen; d += NT)
                sk[d] = g_vkey[jlo + d];
            __syncthreads();
            int p = ib * NT + tid;
            u64 kp = (p < V) ? g_vkey[p] : 0ull;
            int cnt = 0;
#pragma unroll 8
            for (int d = 0; d < mlen; ++d)
                cnt += (sk[d] > kp) ? 1 : 0;
            if (p < V) g_rankp[jb][p] = cnt;
        }
    }
    gbar(2);

    // ---------------- Phase 3: sum partials + scatter -----------------------
    for (int p = gtid; p < V; p += GRID * NT) {
        int r = 0;
#pragma unroll
        for (int y = 0; y < JS; ++y) r += g_rankp[y][p];
        g_sbox[r]   = g_vbox[p];
        g_sscore[r] = g_vscore[p];
    }
    gbar(3);

    // ---------------- Phase 4: IoU -> diag + sparse entries (128x512 tiles)-
    {
        float4* cbox  = (float4*)dyn;              // 512 boxes: 8KB
        float*  carea = (float*)(dyn + 512 * 16);  // 2KB
        int TvR = (V + 127) >> 7;                  // 128-row groups
        int TvC = (V + 511) >> 9;                  // 512-col groups
        int ntasks = 0;
        for (int rb = 0; rb < TvR; ++rb) ntasks += TvC - (rb >> 2);
        for (int task = bid; task < ntasks; task += GRID) {
            int rem = task, rb = 0;
            while (rem >= TvC - (rb >> 2)) { rem -= TvC - (rb >> 2); rb++; }
            int cB = (rb >> 2) + rem;
            __syncthreads();
            if (tid < 512) {
                int j = cB * 512 + tid;
                if (j < V) {
                    float4 b = g_sbox[j];
                    cbox[tid] = b;
                    carea[tid] = __fmul_rn(__fsub_rn(b.z, b.x),
                                           __fsub_rn(b.w, b.y));
                } else {
                    cbox[tid] = make_float4(0.f, 0.f, 0.f, 0.f);
                    carea[tid] = 0.f;
                }
            }
            __syncthreads();
            int row = tid & 127;
            int wq  = tid >> 7;                    // 0..7
            int i = rb * 128 + row;
            int wg = cB * 8 + wq;                  // global mask word
            int dstart = max(0, i + 1 - wg * 64);  // strict upper triangle
            if (i < V && dstart < 64) {
                float4 bi = g_sbox[i];
                float ai = __fmul_rn(__fsub_rn(bi.z, bi.x),
                                     __fsub_rn(bi.w, bi.y));
                int cbase = wq * 64;
                u64 bits = 0ull;
                for (int d = dstart; d < 64; ++d) {
                    float4 bj = cbox[cbase + d];
                    float ltx = fmaxf(bi.x, bj.x);
                    float lty = fmaxf(bi.y, bj.y);
                    float rbx = fminf(bi.z, bj.z);
                    float rby = fminf(bi.w, bj.w);
                    float wx = fmaxf(__fsub_rn(rbx, ltx), 0.0f);
                    float wy = fmaxf(__fsub_rn(rby, lty), 0.0f);
                    float inter = __fmul_rn(wx, wy);
                    float uni = __fsub_rn(__fadd_rn(ai, carea[cbase + d]), inter);
                    float den = fmaxf(uni, 1e-9f);
                    bool hit;
                    if (inter > __fmul_rn(0.5005f, den))      hit = true;
                    else if (inter < __fmul_rn(0.4995f, den)) hit = false;
                    else hit = (__fdiv_rn(inter, den) > IOU_THR);
                    if (hit) bits |= (1ull << d);
                }
                if (wg == (i >> 6)) {
                    g_diag[i] = bits;
                } else if (bits) {
                    unsigned pos = atomicAdd(&g_scount[i], 1u);
                    SpEnt e; e.bits = bits; e.idx = (u64)wg;
                    g_slist[i][pos] = e;
                }
            }
        }
    }
    gbar(4);

    // ---------------- Phase 5: block 0 — batched-scan reduce + output ------
    if (bid != 0) {
        __syncthreads();
        if (tid == 0) atomicAdd(&g_bar_exit, 1);
        return;
    }

    u64* sdiag = (u64*)dyn;                        // [NPAD] 67,584B
    int T = (V + 63) >> 6;
    __syncthreads();
    // init remv: bit p set iff p >= V
    for (int w = tid; w < WORDS; w += NT) {
        int base = w * 64;
        u64 m;
        if (base + 64 <= V)      m = 0ull;
        else if (base >= V)      m = ~0ull;
        else                     m = (~0ull) << (V - base);
        remv[w] = m;
    }
    // one-shot staging of g_diag[0..V)
    {
        int nd = (V + 1) >> 1;
        for (int u = tid; u < nd; u += NT)
            cpa16((uint32_t)__cvta_generic_to_shared(&sdiag[u * 2]),
                  &g_diag[u * 2]);
        asm volatile("cp.async.commit_group;");
        asm volatile("cp.async.wait_group 0;" ::: "memory");
    }
    __syncthreads();
    // nz bitmap over diag words — BOUNDED: r < NPAD (the R10/R11 bug was
    // r reaching 9215 -> s_nz32[287] OOB -> zeroed sdiag[0..11] in dyn smem)
    for (int c = 0; c < NPAD; c += NT) {
        int r = c + tid;
        bool nzb = (r < V) && (r < NPAD) && (sdiag[r] != 0ull);
        unsigned bal = __ballot_sync(0xffffffffu, nzb);
        if ((tid & 31) == 0 && r < NPAD) s_nz32[r >> 5] = bal;
    }
    __syncthreads();

    for (int t = 0; t < T; ++t) {
        if (tid == 0) {
            // batched speculative greedy scan (exact semantics: batch bits
            // ascend; earlier accepted bits suppress later via c-check)
            u64 c = remv[t];
            u64 nz = (u64)s_nz32[2 * t] | ((u64)s_nz32[2 * t + 1] << 32);
            u64 cand = nz & ~c;
            while (cand) {
                int bs[8];
                u64 dv[8];
                u64 tmp = cand;
                int m = 0;
#pragma unroll
                for (int k = 0; k < 8; ++k) {
                    if (tmp) { bs[k] = __ffsll(tmp) - 1; tmp &= tmp - 1; m = k + 1; }
                    else     { bs[k] = 0; }
                }
#pragma unroll
                for (int k = 0; k < 8; ++k)
                    dv[k] = (k < m) ? sdiag[t * 64 + bs[k]] : 0ull;
#pragma unroll
                for (int k = 0; k < 8; ++k)
                    if (k < m && !((c >> bs[k]) & 1ull)) c |= dv[k];
                int blast = bs[m - 1];
                u64 below = (blast == 63) ? ~0ull : ((2ull << blast) - 1ull);
                cand = nz & ~c & ~below;
            }
            remv[t] = c;
        }
        __syncthreads();
        // sparse OR: 64 rows x 16 threads each (massive MLP, SMEM atomicOr)
        {
            int r = t * 64 + (tid >> 4);
            int sub = tid & 15;
            u64 curw = remv[t];
            if (r < V && !((curw >> (r & 63)) & 1ull)) {   // row kept
                int cnt = (int)g_scount[r];
                const SpEnt* lp = &g_slist[r][0];
                for (int e = sub; e < cnt; e += 16) {
                    ulonglong2 ent = *(const ulonglong2*)&lp[e];  // LDG.128
                    int w = (int)ent.y;
                    if (w > t) atomicOr(&remv[w], ent.x);
                }
            }
        }
        __syncthreads();
    }

    // output: kept -> [x1,y1,x2,y2,score], else zeros
    for (int p = tid; p < N; p += NT) {
        bool kept = (p < V) && !((remv[p >> 6] >> (p & 63)) & 1ull);
        float4 b = kept ? g_sbox[p] : make_float4(0.f, 0.f, 0.f, 0.f);
        float s = kept ? g_sscore[p] : 0.f;
        out[p * 5 + 0] = b.x;
        out[p * 5 + 1] = b.y;
        out[p * 5 + 2] = b.z;
        out[p * 5 + 3] = b.w;
        out[p * 5 + 4] = s;
    }

    // reset persistent state for the next graph replay
    __syncthreads();
    if (tid == 0) {
        while (*(volatile int*)&g_bar_exit < GRID - 1) { }
        g_bar_exit = 0;
        g_bar_arrive = 0;
        g_bar_release = 0;
        g_vcount = 0;
        __threadfence();
    }
}

extern "C" void kernel_launch(void* const* d_in, const int* in_sizes, int n_in,
                              void* d_out, int out_size) {
    const float* in = (const float*)d_in[0];
    float* out = (float*)d_out;
    cudaFuncSetAttribute(k_all, cudaFuncAttributeMaxDynamicSharedMemorySize,
                         NPAD * 8);    // 67,584B
    k_all<<<GRID, NT, NPAD * 8>>>(in, out);
}

// round 13
// speedup vs baseline: 3.0024x; 1.0841x over previous
#include <cuda_runtime.h>
#include <cstdint>

#define N 8400
#define WORDS 132          // ceil(8400/64)
#define SCORE_THR 0.5f
#define IOU_THR 0.5f
#define GRID 136           // <= 148 SMs: all blocks co-resident (wave 1)
#define NT 1024
#define JS 32              // rank j-split
#define NPAD 8448          // = 264*32

typedef unsigned long long u64;

struct __align__(16) SpEnt { u64 bits; u64 idx; };

// ---- persistent device state (allocation-free rule) ----
__device__ int g_vcount = 0;
__device__ int g_bar_arrive = 0;
__device__ volatile int g_bar_release = 0;
__device__ int g_bar_exit = 0;
__device__ u64 g_vkey[N];
__device__ float4 g_vbox[N];
__device__ float g_vscore[N];
__device__ int g_rankp[JS][N];
__device__ float4 g_sbox[N];
__device__ float g_sscore[N];
__device__ u64 g_diag2[NPAD][2];           // dense near-diag: own word, next word
__device__ unsigned g_scount[NPAD];        // # sparse entries (wg >= own+2)
__device__ SpEnt g_slist[N][WORDS];        // sparse far-off-diag words

// Software grid barrier (all CTAs co-resident since GRID < #SMs).
__device__ __forceinline__ void gbar(int gen) {
    __syncthreads();
    if (threadIdx.x == 0) {
        __threadfence();
        int prev = atomicAdd(&g_bar_arrive, 1);
        if (prev == gen * GRID - 1) {
            g_bar_release = gen;
        } else {
            while (g_bar_release < gen) { }
        }
        __threadfence();
    }
    __syncthreads();
}

__device__ __forceinline__ void cpa16(uint32_t saddr, const void* gptr) {
    asm volatile("cp.async.cg.shared.global [%0], [%1], 16;"
                 :: "r"(saddr), "l"(gptr));
}

// batched greedy scan of one 64-row word; kept bit b ORs d0 -> cown, d1 -> cnext
__device__ __forceinline__ void scan_word(const u64 (*sd2)[2], int base, u64 nz,
                                          u64& cown, u64& cnext) {
    u64 cand = nz & ~cown;
    while (cand) {
        int bs[8]; u64 v0[8], v1[8];
        u64 tmp = cand; int m = 0;
#pragma unroll
        for (int k = 0; k < 8; ++k) {
            if (tmp) { bs[k] = __ffsll(tmp) - 1; tmp &= tmp - 1; m = k + 1; }
            else     { bs[k] = 0; }
        }
#pragma unroll
        for (int k = 0; k < 8; ++k) {
            v0[k] = (k < m) ? sd2[base + bs[k]][0] : 0ull;
            v1[k] = (k < m) ? sd2[base + bs[k]][1] : 0ull;
        }
#pragma unroll
        for (int k = 0; k < 8; ++k)
            if (k < m && !((cown >> bs[k]) & 1ull)) { cown |= v0[k]; cnext |= v1[k]; }
        int blast = bs[m - 1];
        u64 below = (blast == 63) ? ~0ull : ((2ull << blast) - 1ull);
        cand = nz & ~cown & ~below;
    }
}

__global__ __launch_bounds__(NT) void k_all(const float* __restrict__ in,
                                            float* __restrict__ out) {
    extern __shared__ __align__(16) char dyn[];   // 168,960B
    __shared__ u64 remv[WORDS + 2];
    __shared__ unsigned s_nz32[2 * WORDS];
    int tid = threadIdx.x;
    int bid = blockIdx.x;
    int gtid = bid * NT + tid;

    // ---------------- Phase 1: decode + compact valid ----------------------
    {
        int a = gtid;
        int lane = tid & 31;
        bool valid = false;
        float4 b = make_float4(0.f, 0.f, 0.f, 0.f);
        float s = 0.f;
        u64 key = 0ull;
        if (a < N) {
            float cx = in[a];
            float cy = in[N + a];
            float w  = in[2 * N + a];
            float h  = in[3 * N + a];
            s = in[4 * N + a];
            float hw = __fmul_rn(w, 0.5f);
            float hh = __fmul_rn(h, 0.5f);
            b.x = __fsub_rn(cx, hw);
            b.y = __fsub_rn(cy, hh);
            b.z = __fadd_rn(cx, hw);
            b.w = __fadd_rn(cy, hh);
            valid = (s >= SCORE_THR);
            key = (((u64)__float_as_uint(s)) << 14) | (u64)(16383 - a);
            g_scount[a] = 0u;
            g_diag2[a][0] = 0ull;
            g_diag2[a][1] = 0ull;
        }
        unsigned m = __ballot_sync(0xffffffffu, valid);
        if (m != 0u) {
            int leader = __ffs(m) - 1;
            int base = 0;
            if (lane == leader) base = atomicAdd(&g_vcount, __popc(m));
            base = __shfl_sync(0xffffffffu, base, leader);
            if (valid) {
                int pos = base + __popc(m & ((1u << lane) - 1u));
                g_vkey[pos]   = key;
                g_vbox[pos]   = b;
                g_vscore[pos] = s;
            }
        }
    }
    gbar(1);
    int V = *(volatile int*)&g_vcount;

    // ---------------- Phase 2: rank partials (i-blocks x 32 j-chunks) ------
    {
        u64* sk = (u64*)dyn;
        int IB = (V + NT - 1) / NT;
        int CH = (V + JS - 1) / JS;
        int ntasks = IB * JS;
        for (int task = bid; task < ntasks; task += GRID) {
            int ib = task % IB;
            int jb = task / IB;
            int jlo = jb * CH;
            int mlen = min(jlo + CH, V) - jlo;
            __syncthreads();
            for (int d = tid; d < mlen; d += NT)
                sk[d] = g_vkey[jlo + d];
            __syncthreads();
            int p = ib * NT + tid;
            u64 kp = (p < V) ? g_vkey[p] : 0ull;
            int cnt = 0;
#pragma unroll 8
            for (int d = 0; d < mlen; ++d)
                cnt += (sk[d] > kp) ? 1 : 0;
            if (p < V) g_rankp[jb][p] = cnt;
        }
    }
    gbar(2);

    // ---------------- Phase 3: sum partials + scatter -----------------------
    for (int p = gtid; p < V; p += GRID * NT) {
        int r = 0;
#pragma unroll
        for (int y = 0; y < JS; ++y) r += g_rankp[y][p];
        g_sbox[r]   = g_vbox[p];
        g_sscore[r] = g_vscore[p];
    }
    gbar(3);

    // ---------------- Phase 4: IoU -> diag2 + sparse entries ---------------
    {
        float4* cbox  = (float4*)dyn;              // 512 boxes
        float*  carea = (float*)(dyn + 512 * 16);
        int TvR = (V + 127) >> 7;
        int TvC = (V + 511) >> 9;
        int ntasks = 0;
        for (int rb = 0; rb < TvR; ++rb) ntasks += TvC - (rb >> 2);
        for (int task = bid; task < ntasks; task += GRID) {
            int rem = task, rb = 0;
            while (rem >= TvC - (rb >> 2)) { rem -= TvC - (rb >> 2); rb++; }
            int cB = (rb >> 2) + rem;
            __syncthreads();
            if (tid < 512) {
                int j = cB * 512 + tid;
                if (j < V) {
                    float4 b = g_sbox[j];
                    cbox[tid] = b;
                    carea[tid] = __fmul_rn(__fsub_rn(b.z, b.x),
                                           __fsub_rn(b.w, b.y));
                } else {
                    cbox[tid] = make_float4(0.f, 0.f, 0.f, 0.f);
                    carea[tid] = 0.f;
                }
            }
            __syncthreads();
            int row = tid & 127;
            int wq  = tid >> 7;
            int i = rb * 128 + row;
            int wg = cB * 8 + wq;
            int dstart = max(0, i + 1 - wg * 64);
            if (i < V && dstart < 64) {
                float4 bi = g_sbox[i];
                float ai = __fmul_rn(__fsub_rn(bi.z, bi.x),
                                     __fsub_rn(bi.w, bi.y));
                int cbase = wq * 64;
                u64 bits = 0ull;
                for (int d = dstart; d < 64; ++d) {
                    float4 bj = cbox[cbase + d];
                    float ltx = fmaxf(bi.x, bj.x);
                    float lty = fmaxf(bi.y, bj.y);
                    float rbx = fminf(bi.z, bj.z);
                    float rby = fminf(bi.w, bj.w);
                    float wx = fmaxf(__fsub_rn(rbx, ltx), 0.0f);
                    float wy = fmaxf(__fsub_rn(rby, lty), 0.0f);
                    float inter = __fmul_rn(wx, wy);
                    float uni = __fsub_rn(__fadd_rn(ai, carea[cbase + d]), inter);
                    float den = fmaxf(uni, 1e-9f);
                    bool hit;
                    if (inter > __fmul_rn(0.5005f, den))      hit = true;
                    else if (inter < __fmul_rn(0.4995f, den)) hit = false;
                    else hit = (__fdiv_rn(inter, den) > IOU_THR);
                    if (hit) bits |= (1ull << d);
                }
                int own = i >> 6;
                if (wg == own) {
                    g_diag2[i][0] = bits;
                } else if (wg == own + 1) {
                    g_diag2[i][1] = bits;
                } else if (bits) {
                    unsigned pos = atomicAdd(&g_scount[i], 1u);
                    SpEnt e; e.bits = bits; e.idx = (u64)wg;
                    g_slist[i][pos] = e;
                }
            }
        }
    }
    gbar(4);

    // ---------------- Phase 5: block 0 — supertile reduce + output ---------
    if (bid != 0) {
        __syncthreads();
        if (tid == 0) atomicAdd(&g_bar_exit, 1);
        return;
    }

    u64 (*sd2)[2] = (u64 (*)[2])dyn;               // [NPAD][2] 135,168B
    unsigned* sscnt = (unsigned*)(dyn + NPAD * 16);// [NPAD]     33,792B
    int T = (V + 63) >> 6;
    int TT = (T + 1) >> 1;
    __syncthreads();
    // init remv (incl. 2 spill words): bit p set iff p >= V
    for (int w = tid; w < WORDS + 2; w += NT) {
        int base = w * 64;
        u64 m;
        if (base + 64 <= V)      m = 0ull;
        else if (base >= V)      m = ~0ull;
        else                     m = (~0ull) << (V - base);
        remv[w] = m;
    }
    // one-shot staging: diag2 rows [0,V) + scount
    {
        for (int u = tid; u < V; u += NT)
            cpa16((uint32_t)__cvta_generic_to_shared(&sd2[u][0]), &g_diag2[u][0]);
        int ns = (V + 3) >> 2;
        for (int u = tid; u < ns; u += NT)
            cpa16((uint32_t)__cvta_generic_to_shared(&sscnt[u * 4]),
                  &g_scount[u * 4]);
        asm volatile("cp.async.commit_group;");
        asm volatile("cp.async.wait_group 0;" ::: "memory");
    }
    __syncthreads();
    // nz bitmap over (d0|d1), bounded to NPAD
    for (int c = 0; c < NPAD; c += NT) {
        int r = c + tid;
        bool nzb = (r < V) && ((sd2[r][0] | sd2[r][1]) != 0ull);
        unsigned bal = __ballot_sync(0xffffffffu, nzb);
        if ((tid & 31) == 0 && r < NPAD) s_nz32[r >> 5] = bal;
    }
    __syncthreads();

    for (int t = 0; t < TT; ++t) {
        int w0 = 2 * t, w1 = 2 * t + 1;
        if (tid == 0) {
            u64 c0 = remv[w0];
            u64 c1 = remv[w1];
            u64 ext = 0ull;
            u64 nz0 = (u64)s_nz32[2 * w0] | ((u64)s_nz32[2 * w0 + 1] << 32);
            scan_word(sd2, w0 * 64, nz0, c0, c1);
            if (w1 < T) {
                u64 nz1 = (u64)s_nz32[2 * w1] | ((u64)s_nz32[2 * w1 + 1] << 32);
                scan_word(sd2, w1 * 64, nz1, c1, ext);
            }
            remv[w0] = c0;
            remv[w1] = c1;
            remv[w1 + 1] |= ext;
        }
        __syncthreads();
        // OR phase: 128 rows x 8 threads; all entries target words > w1
        {
            int rr = tid >> 3;                      // 0..127
            int sub = tid & 7;
            int r = w0 * 64 + rr;
            u64 curw = remv[w0 + (rr >> 6)];
            if (r < V && !((curw >> (r & 63)) & 1ull)) {   // row kept
                int cnt = (int)sscnt[r];
                const SpEnt* lp = &g_slist[r][0];
                for (int e = sub; e < cnt; e += 8) {
                    ulonglong2 ent = *(const ulonglong2*)&lp[e];  // LDG.128
                    atomicOr(&remv[(int)ent.y], ent.x);
                }
            }
        }
        __syncthreads();
    }

    // output: kept -> [x1,y1,x2,y2,score], else zeros
    for (int p = tid; p < N; p += NT) {
        bool kept = (p < V) && !((remv[p >> 6] >> (p & 63)) & 1ull);
        float4 b = kept ? g_sbox[p] : make_float4(0.f, 0.f, 0.f, 0.f);
        float s = kept ? g_sscore[p] : 0.f;
        out[p * 5 + 0] = b.x;
        out[p * 5 + 1] = b.y;
        out[p * 5 + 2] = b.z;
        out[p * 5 + 3] = b.w;
        out[p * 5 + 4] = s;
    }

    // reset persistent state for the next graph replay
    __syncthreads();
    if (tid == 0) {
        while (*(volatile int*)&g_bar_exit < GRID - 1) { }
        g_bar_exit = 0;
        g_bar_arrive = 0;
        g_bar_release = 0;
        g_vcount = 0;
        __threadfence();
    }
}

extern "C" void kernel_launch(void* const* d_in, const int* in_sizes, int n_in,
                              void* d_out, int out_size) {
    const float* in = (const float*)d_in[0];
    float* out = (float*)d_out;
    cudaFuncSetAttribute(k_all, cudaFuncAttributeMaxDynamicSharedMemorySize,
                         NPAD * 20);   // 168,960B
    k_all<<<GRID, NT, NPAD * 20>>>(in, out);
}